// round 16
// baseline (speedup 1.0000x reference)
#include <cuda_runtime.h>
#include <cuda_bf16.h>
#include <cuda_fp16.h>
#include <math.h>
#include <cstdint>

// Problem constants (fixed by setup_inputs)
#define Nn   32000
#define Hh   128
#define Ll   3
#define Rr   8
#define Ee   512000
#define BSz  32
#define Kk   64
#define NPG  1000
#define KK   1152        // R*H + H
#define NCHK 18          // K chunks of 64
#define NBINS 32768

// Scratch (device globals; no runtime allocation allowed)
__device__ float g_repr[(size_t)Ll * Nn * Hh];
__device__ float g_mean_buf[BSz * Ll * Hh];
__device__ float g_pool_part[BSz * Ll * 8 * Hh];
// A matrix fp16, CHUNK-MAJOR + SW128-swizzled: [chunk 18][node][64]
// chunks 0..15 = agg (rel r -> 2r,2r+1), 16,17 = current-layer input h (fp16)
__device__ __half g_A[(size_t)NCHK * Nn * 64];
// Weights fp16, chunk-major swizzled: [L][chunk 18][n 128][64]
__device__ __half g_W[(size_t)Ll * Hh * KK];
// CSR by dst
__device__ int g_cnt[NBINS];
__device__ int g_off[NBINS];
__device__ int g_fill[NBINS];
__device__ uint32_t g_edges[Ee];   // src | (et << 16)

__device__ __forceinline__ uint32_t smem_to_u32(const void* smem_ptr) {
    uint32_t addr;
    asm("{ .reg .u64 tmp; cvta.to.shared.u64 tmp, %1; cvt.u32.u64 %0, tmp; }"
        : "=r"(addr) : "l"(smem_ptr));
    return addr;
}
#define MBARRIER_INIT(mbar, count) \
    asm volatile("mbarrier.init.shared.b64 [%0], %1;" \
        :: "r"((uint32_t)(mbar)), "r"((uint32_t)(count)) : "memory")
#define MBARRIER_EXPECT_TX(mbar, tx) \
    asm volatile("mbarrier.arrive.expect_tx.shared.b64 _, [%0], %1;" \
        :: "r"((uint32_t)(mbar)), "r"((uint32_t)(tx)) : "memory")
#define MBARRIER_WAIT_PARITY(mbar, parity) do { \
    uint32_t _mbar = (uint32_t)(mbar); \
    uint32_t _parity = (uint32_t)(parity); \
    uint32_t _done; \
    asm volatile( \
        "{\n\t.reg .pred p;\n\t" \
        "mbarrier.try_wait.parity.acquire.cta.shared::cta.b64 p, [%1], %2;\n\t" \
        "selp.b32 %0, 1, 0, p;\n\t}" \
        : "=r"(_done) : "r"(_mbar), "r"(_parity) : "memory"); \
    if (!_done) { \
        asm volatile( \
            "{\n\t.reg .pred P1;\n\t" \
            "WAIT_LOOP_%=:\n\t" \
            "mbarrier.try_wait.parity.acquire.cta.shared::cta.b64 P1, [%0], %1, 0x989680;\n\t" \
            "@P1 bra.uni WAIT_DONE_%=;\n\t" \
            "bra.uni WAIT_LOOP_%=;\n\t" \
            "WAIT_DONE_%=:\n\t}" \
            :: "r"(_mbar), "r"(_parity) : "memory"); \
    } \
} while(0)
__device__ __forceinline__ void bulkcp(uint32_t dst, const void* src,
                                       uint32_t bytes, uint32_t mbar) {
    asm volatile(
        "cp.async.bulk.shared::cluster.global.mbarrier::complete_tx::bytes "
        "[%0], [%1], %2, [%3];"
        :: "r"(dst), "l"(src), "r"(bytes), "r"(mbar) : "memory");
}

// swizzled element offset within a chunk row (64 fp16 = 128B row), row = node
__device__ __forceinline__ uint32_t swz64(int node, int c6) {
    return (uint32_t)(((((c6 >> 3) ^ (node & 7)) & 7) << 3) + (c6 & 7));
}

// ---------------------------------------------------------------------------
// CSR build (key = dst)
// ---------------------------------------------------------------------------
__global__ void zero_cnt_kernel() {
    int i = blockIdx.x * blockDim.x + threadIdx.x;
    g_cnt[i] = 0;
}
__global__ void count_kernel(const int* __restrict__ dst) {
    int e = blockIdx.x * blockDim.x + threadIdx.x;
    if (e < Ee) atomicAdd(&g_cnt[dst[e]], 1);
}
__global__ void scan_kernel() {
    __shared__ int wsum[32];
    int tid = threadIdx.x, lane = tid & 31, wid = tid >> 5;
    int carry = 0;
    for (int c = 0; c < NBINS / 1024; c++) {
        int idx = c * 1024 + tid;
        int v = g_cnt[idx];
        int incl = v;
        #pragma unroll
        for (int d = 1; d < 32; d <<= 1) {
            int n = __shfl_up_sync(0xffffffff, incl, d);
            if (lane >= d) incl += n;
        }
        if (lane == 31) wsum[wid] = incl;
        __syncthreads();
        if (wid == 0) {
            int s = wsum[lane];
            #pragma unroll
            for (int d = 1; d < 32; d <<= 1) {
                int n = __shfl_up_sync(0xffffffff, s, d);
                if (lane >= d) s += n;
            }
            wsum[lane] = s;
        }
        __syncthreads();
        int warp_prefix = wid ? wsum[wid - 1] : 0;
        int excl = carry + warp_prefix + incl - v;
        g_off[idx] = excl;
        g_fill[idx] = excl;
        carry += wsum[31];
        __syncthreads();
    }
}
__global__ void fill_kernel(const int* __restrict__ src,
                            const int* __restrict__ dst,
                            const int* __restrict__ et) {
    int e = blockIdx.x * blockDim.x + threadIdx.x;
    if (e >= Ee) return;
    int d = dst[e];
    int pos = atomicAdd(&g_fill[d], 1);
    g_edges[pos] = (uint32_t)src[e] | ((uint32_t)et[e] << 16);
}

// ---------------------------------------------------------------------------
// Weight pre-conversion into chunk-major swizzled layout, single fp16
// ---------------------------------------------------------------------------
__global__ void conv_w_kernel(const float* __restrict__ W_rel,
                              const float* __restrict__ W_self) {
    size_t idx = (size_t)blockIdx.x * blockDim.x + threadIdx.x;
    if (idx >= (size_t)Ll * Hh * KK) return;
    int k = (int)(idx % KK);
    int n = (int)((idx / KK) % Hh);
    int l = (int)(idx / ((size_t)KK * Hh));
    float w = (k < Rr * Hh)
        ? W_rel[((size_t)l * Rr * Hh + k) * Hh + n]
        : W_self[((size_t)l * Hh + (k - Rr * Hh)) * Hh + n];
    int chunk = k >> 6, c6 = k & 63;
    size_t o = ((size_t)(l * NCHK + chunk) * Hh + n) * 64 + swz64(n, c6);
    g_W[o] = __float2half(w);
}

// ---------------------------------------------------------------------------
// x -> fp16 into self chunks 16,17
// ---------------------------------------------------------------------------
__global__ void xsplit_kernel(const float* __restrict__ x) {
    int pos = blockIdx.x * blockDim.x + threadIdx.x;
    if (pos >= Nn * Hh / 4) return;
    int row = pos >> 5, c4 = (pos & 31) * 4;
    float4 v = *(const float4*)(x + (size_t)row * Hh + c4);
    __half h0 = __float2half(v.x), h1 = __float2half(v.y);
    __half h2 = __float2half(v.z), h3 = __float2half(v.w);
    uint2 u;
    u.x = (uint32_t)__half_as_ushort(h0) | ((uint32_t)__half_as_ushort(h1) << 16);
    u.y = (uint32_t)__half_as_ushort(h2) | ((uint32_t)__half_as_ushort(h3) << 16);
    int chunk = 16 + (c4 >> 6), c6 = c4 & 63;
    size_t o = ((size_t)chunk * Nn + row) * 64 + swz64(row, c6);
    *(uint2*)(g_A + o) = u;
}

// ---------------------------------------------------------------------------
// Gather: warp per dst node; 4-wide unrolled; reads fp16 h from g_A chunks
// 16/17 (swizzled, LDG.64 per lane), accumulates fp32, writes fp16 chunks 0..15.
// ---------------------------------------------------------------------------
__global__ __launch_bounds__(256)
void gather_kernel() {
    int gw = (blockIdx.x * blockDim.x + threadIdx.x) >> 5;
    int lane = threadIdx.x & 31;
    if (gw >= Nn) return;
    int beg = g_off[gw];
    int cnt = g_cnt[gw];

    // fp16 h source: chunk 16 + (lane>>4), columns (lane&15)*4 .. +3
    const int hs = lane >> 4;                    // chunk half
    const int c6h = (lane & 15) * 4;
    const __half* hbase = g_A + (size_t)(16 + hs) * Nn * 64;
    // per-node swizzle: off = ((((c6h>>3) ^ (s&7)) & 7) << 3) + (c6h & 7)
    const int c6hi = c6h >> 3, c6lo = c6h & 7;

    float4 a0 = {0,0,0,0}, a1 = {0,0,0,0}, a2 = {0,0,0,0}, a3 = {0,0,0,0};
    float4 a4 = {0,0,0,0}, a5 = {0,0,0,0}, a6 = {0,0,0,0}, a7 = {0,0,0,0};

    #define LOAD_H(s, v) do { \
        uint32_t off = ((uint32_t)(((c6hi ^ ((s) & 7)) & 7) << 3)) + c6lo; \
        uint2 u = *(const uint2*)(hbase + (size_t)(s) * 64 + off); \
        float2 f01 = __half22float2(*(const __half2*)&u.x); \
        float2 f23 = __half22float2(*(const __half2*)&u.y); \
        v.x = f01.x; v.y = f01.y; v.z = f23.x; v.w = f23.y; \
    } while (0)

    #define ACC_ADD(p, v) do { \
        switch ((p) >> 16) { \
            case 0: a0.x+=v.x; a0.y+=v.y; a0.z+=v.z; a0.w+=v.w; break; \
            case 1: a1.x+=v.x; a1.y+=v.y; a1.z+=v.z; a1.w+=v.w; break; \
            case 2: a2.x+=v.x; a2.y+=v.y; a2.z+=v.z; a2.w+=v.w; break; \
            case 3: a3.x+=v.x; a3.y+=v.y; a3.z+=v.z; a3.w+=v.w; break; \
            case 4: a4.x+=v.x; a4.y+=v.y; a4.z+=v.z; a4.w+=v.w; break; \
            case 5: a5.x+=v.x; a5.y+=v.y; a5.z+=v.z; a5.w+=v.w; break; \
            case 6: a6.x+=v.x; a6.y+=v.y; a6.z+=v.z; a6.w+=v.w; break; \
            default: a7.x+=v.x; a7.y+=v.y; a7.z+=v.z; a7.w+=v.w; break; \
        } \
    } while (0)

    for (int base = 0; base < cnt; base += 32) {
        int m = min(32, cnt - base);
        uint32_t myp = (lane < m) ? g_edges[beg + base + lane] : 0u;
        int j = 0;
        for (; j + 3 < m; j += 4) {
            uint32_t p0 = __shfl_sync(0xffffffffu, myp, j);
            uint32_t p1 = __shfl_sync(0xffffffffu, myp, j + 1);
            uint32_t p2 = __shfl_sync(0xffffffffu, myp, j + 2);
            uint32_t p3 = __shfl_sync(0xffffffffu, myp, j + 3);
            float4 v0, v1, v2, v3;
            LOAD_H((int)(p0 & 0xffffu), v0);
            LOAD_H((int)(p1 & 0xffffu), v1);
            LOAD_H((int)(p2 & 0xffffu), v2);
            LOAD_H((int)(p3 & 0xffffu), v3);
            ACC_ADD(p0, v0); ACC_ADD(p1, v1); ACC_ADD(p2, v2); ACC_ADD(p3, v3);
        }
        for (; j < m; j++) {
            uint32_t p = __shfl_sync(0xffffffffu, myp, j);
            float4 v;
            LOAD_H((int)(p & 0xffffu), v);
            ACC_ADD(p, v);
        }
    }
    #undef ACC_ADD
    #undef LOAD_H

    // write: lane covers cols lane*4..lane*4+3 of 128; chunk = 2r + (lane>>4)
    uint32_t sw = swz64(gw, c6h);
    #define FP16_WRITE(acc, rr) do { \
        __half h0 = __float2half(acc.x), h1 = __float2half(acc.y); \
        __half h2 = __float2half(acc.z), h3 = __float2half(acc.w); \
        uint2 u; \
        u.x = (uint32_t)__half_as_ushort(h0) | ((uint32_t)__half_as_ushort(h1) << 16); \
        u.y = (uint32_t)__half_as_ushort(h2) | ((uint32_t)__half_as_ushort(h3) << 16); \
        size_t o = ((size_t)(2 * (rr) + hs) * Nn + gw) * 64 + sw; \
        *(uint2*)(g_A + o) = u; \
    } while (0)
    FP16_WRITE(a0, 0); FP16_WRITE(a1, 1); FP16_WRITE(a2, 2); FP16_WRITE(a3, 3);
    FP16_WRITE(a4, 4); FP16_WRITE(a5, 5); FP16_WRITE(a6, 6); FP16_WRITE(a7, 7);
    #undef FP16_WRITE
}

// ---------------------------------------------------------------------------
// mma.sync fp16 GEMM with cp.async.bulk staging, single pass.
// CTA: 256 rows x 128 cols, 8 warps (4M x 2N), warp tile 64x64.
// 18 chunks of K=64; 4-deep mbarrier pipeline.
// ---------------------------------------------------------------------------
#define TILE_A 32768                 // 256 rows * 128B
#define TILE_B 16384                 // 128 rows * 128B
#define STAGEB (TILE_A + TILE_B)     // 49152
#define NSTAGE 4
#define MBAR_OFF (NSTAGE * STAGEB)   // 196608
#define SM_TOTAL (MBAR_OFF + 64)

__device__ __forceinline__ void ldsm_x4(uint32_t* r, uint32_t addr) {
    asm volatile("ldmatrix.sync.aligned.m8n8.x4.shared.b16 {%0,%1,%2,%3}, [%4];"
                 : "=r"(r[0]), "=r"(r[1]), "=r"(r[2]), "=r"(r[3]) : "r"(addr));
}
__device__ __forceinline__ void ldsm_x2(uint32_t* r, uint32_t addr) {
    asm volatile("ldmatrix.sync.aligned.m8n8.x2.shared.b16 {%0,%1}, [%2];"
                 : "=r"(r[0]), "=r"(r[1]) : "r"(addr));
}
__device__ __forceinline__ void mma16816f16(float* c, const uint32_t* a, const uint32_t* b) {
    asm volatile(
        "mma.sync.aligned.m16n8k16.row.col.f32.f16.f16.f32 "
        "{%0,%1,%2,%3}, {%4,%5,%6,%7}, {%8,%9}, {%0,%1,%2,%3};"
        : "+f"(c[0]), "+f"(c[1]), "+f"(c[2]), "+f"(c[3])
        : "r"(a[0]), "r"(a[1]), "r"(a[2]), "r"(a[3]), "r"(b[0]), "r"(b[1]));
}

__global__ __launch_bounds__(256, 1)
void rgcn_mma_gemm_kernel(const __half* __restrict__ W,   // layer chunk-major
                          float* __restrict__ out,
                          int write_self) {
    extern __shared__ char dsm[];
    const uint32_t sb = smem_to_u32(dsm);
    const int tid  = threadIdx.x;
    const int wid  = tid >> 5;
    const int lane = tid & 31;
    const int warp_m = wid >> 1;       // 0..3 (64-row tiles)
    const int warp_n = wid & 1;        // 0..1 (64-col tiles)
    const int row0 = blockIdx.x * 256;

    if (tid == 0) {
        #pragma unroll
        for (int s = 0; s < NSTAGE; s++) MBARRIER_INIT(sb + MBAR_OFF + s * 8, 1);
    }
    asm volatile("fence.proxy.async.shared::cta;" ::: "memory");
    __syncthreads();

    auto issue = [&](int t, int slot) {
        if (tid == 0) {
            uint32_t mbar = sb + MBAR_OFF + slot * 8;
            MBARRIER_EXPECT_TX(mbar, STAGEB);
            uint32_t s = sb + slot * STAGEB;
            const __half* a = g_A + ((size_t)t * Nn + row0) * 64;
            bulkcp(s,          a, TILE_A, mbar);
            bulkcp(s + TILE_A, W + (size_t)t * Hh * 64, TILE_B, mbar);
        }
    };

    float acc[4][8][4];
    #pragma unroll
    for (int mt = 0; mt < 4; mt++)
        #pragma unroll
        for (int nt = 0; nt < 8; nt++)
            #pragma unroll
            for (int j = 0; j < 4; j++) acc[mt][nt][j] = 0.f;

    issue(0, 0);
    issue(1, 1);
    issue(2, 2);
    issue(3, 3);

    for (int t = 0; t < NCHK; t++) {
        int slot = t % NSTAGE;
        MBARRIER_WAIT_PARITY(sb + MBAR_OFF + slot * 8, (t / NSTAGE) & 1);

        uint32_t S  = sb + slot * STAGEB;
        uint32_t AH = S;
        uint32_t BH = S + TILE_A;

        #pragma unroll
        for (int ks = 0; ks < 4; ks++) {
            uint32_t bf[8][2];
            {
                int cb = (lane >> 3) & 1;
                #pragma unroll
                for (int nt = 0; nt < 8; nt++) {
                    int nl = warp_n * 64 + nt * 8 + (lane & 7);
                    uint32_t a = (uint32_t)(nl * 128 + (((ks * 2 + cb) ^ (nl & 7)) << 4));
                    ldsm_x2(bf[nt], BH + a);
                }
            }
            uint32_t af[4][4];
            int cb = lane >> 4;
            #pragma unroll
            for (int mt = 0; mt < 4; mt++) {
                int rl = warp_m * 64 + mt * 16 + (lane & 15);
                ldsm_x4(af[mt], AH + (uint32_t)(rl * 128 + (((ks * 2 + cb) ^ (rl & 7)) << 4)));
            }
            #pragma unroll
            for (int mt = 0; mt < 4; mt++)
                #pragma unroll
                for (int nt = 0; nt < 8; nt++)
                    mma16816f16(acc[mt][nt], af[mt], bf[nt]);
        }
        __syncthreads();                 // all warps done with this slot
        if (t + NSTAGE < NCHK) issue(t + NSTAGE, slot);
    }

    // ---- epilogue: relu + fp32 repr (+ fp16 self chunks unless last layer) ----
    #pragma unroll
    for (int mt = 0; mt < 4; mt++) {
        int row = row0 + warp_m * 64 + mt * 16 + (lane >> 2);
        #pragma unroll
        for (int nt = 0; nt < 8; nt++) {
            int col = warp_n * 64 + nt * 8 + (lane & 3) * 2;
            int chunk = 16 + (col >> 6), c6 = col & 63;
            #pragma unroll
            for (int half_i = 0; half_i < 2; half_i++) {
                int rr = row + half_i * 8;
                float ox = fmaxf(acc[mt][nt][half_i * 2 + 0], 0.f);
                float oy = fmaxf(acc[mt][nt][half_i * 2 + 1], 0.f);
                *(float2*)(out + (size_t)rr * Hh + col) = make_float2(ox, oy);
                if (write_self) {
                    __half h0 = __float2half(ox);
                    __half h1 = __float2half(oy);
                    uint32_t u = (uint32_t)__half_as_ushort(h0) | ((uint32_t)__half_as_ushort(h1) << 16);
                    size_t so = ((size_t)chunk * Nn + rr) * 64 + swz64(rr, c6);
                    *(uint32_t*)(g_A + so) = u;
                }
            }
        }
    }
}

// ---------------------------------------------------------------------------
// Mean pooling: two-stage deterministic
// ---------------------------------------------------------------------------
__global__ void pool_part_kernel() {
    int bl = blockIdx.x;
    int ck = blockIdx.y;
    int b = bl / Ll, l = bl % Ll, i = threadIdx.x;
    int n0 = ck * (NPG / 8);
    const float* p = g_repr + (size_t)l * Nn * Hh + (size_t)(b * NPG + n0) * Hh + i;
    float s = 0.f;
    for (int n = 0; n < NPG / 8; n++) s += p[(size_t)n * Hh];
    g_pool_part[(bl * 8 + ck) * Hh + i] = s;
}
__global__ void pool_combine_kernel() {
    int bl = blockIdx.x, i = threadIdx.x;
    float s = 0.f;
    #pragma unroll
    for (int ck = 0; ck < 8; ck++) s += g_pool_part[(bl * 8 + ck) * Hh + i];
    g_mean_buf[bl * Hh + i] = s * (1.0f / NPG);
}

// ---------------------------------------------------------------------------
// Fused final head
// ---------------------------------------------------------------------------
__global__ void final_kernel(const float* __restrict__ rel_table,
                             const float* __restrict__ Zn,
                             const float* __restrict__ proj_W,
                             const float* __restrict__ proj_b,
                             const float* __restrict__ fc_W,
                             const float* __restrict__ fc_b,
                             const float* __restrict__ rep_seq,
                             const int* __restrict__ head_ids,
                             const int* __restrict__ tail_ids,
                             const int* __restrict__ rel_labels,
                             float* __restrict__ out)
{
    int b = blockIdx.x, i = threadIdx.x;
    __shared__ float sh_head[Ll * Hh], sh_tail[Ll * Hh], sh_gm[Ll * Hh];
    __shared__ float sh_gout[Hh], sh_hout[Hh], sh_tout[Hh];
    __shared__ float sh_e1[Kk], sh_e2[Kk];
    __shared__ float red[Hh];

    int head = head_ids[b], tail = tail_ids[b], rl = rel_labels[b];

    for (int j = i; j < Ll * Hh; j += Hh) {
        int l = j >> 7, c = j & 127;
        sh_head[j] = g_repr[(size_t)l * Nn * Hh + (size_t)head * Hh + c];
        sh_tail[j] = g_repr[(size_t)l * Nn * Hh + (size_t)tail * Hh + c];
        sh_gm[j]   = g_mean_buf[(b * Ll + l) * Hh + c];
    }
    __syncthreads();

    float bias = proj_b[i];
    float ag = bias, ah = bias, at = bias;
    for (int j = 0; j < Ll * Hh; j++) {
        float w = proj_W[j * Hh + i];
        ag = fmaf(sh_gm[j],   w, ag);
        ah = fmaf(sh_head[j], w, ah);
        at = fmaf(sh_tail[j], w, at);
    }
    sh_gout[i] = (ag >= 0.f) ? ag : 0.01f * ag;
    sh_hout[i] = ah;
    sh_tout[i] = at;
    __syncthreads();

    float lg1 = 0.f, lg2 = 0.f;
    if (i < Kk) {
        const float* z = Zn + (size_t)i * Hh;
        for (int c = 0; c < Hh; c++) {
            lg1 = fmaf(sh_hout[c], z[c], lg1);
            lg2 = fmaf(sh_tout[c], z[c], lg2);
        }
        sh_e1[i] = lg1; sh_e2[i] = lg2;
    }
    __syncthreads();
    float m1 = -1e30f, m2 = -1e30f;
    for (int k = 0; k < Kk; k++) {
        m1 = fmaxf(m1, sh_e1[k]);
        m2 = fmaxf(m2, sh_e2[k]);
    }
    __syncthreads();
    if (i < Kk) { sh_e1[i] = expf(lg1 - m1); sh_e2[i] = expf(lg2 - m2); }
    __syncthreads();
    float sum1 = 0.f, sum2 = 0.f;
    for (int k = 0; k < Kk; k++) { sum1 += sh_e1[k]; sum2 += sh_e2[k]; }
    float a1 = 0.f, a2 = 0.f;
    for (int k = 0; k < Kk; k++) {
        float zi = Zn[(size_t)k * Hh + i];
        a1 = fmaf(sh_e1[k], zi, a1);
        a2 = fmaf(sh_e2[k], zi, a2);
    }
    a1 /= sum1; a2 /= sum2;
    float sview = (1.f / (1.f + expf(-a1))) * (1.f / (1.f + expf(-a2)));

    float relv = rel_table[(size_t)rl * Hh + i];
    float v0 = sh_gout[i];
    float v1 = rep_seq[(size_t)b * Hh + i];
    float v2 = sview;

    float d[3];
    float parts[3] = {relv * v0, relv * v1, relv * v2};
    #pragma unroll
    for (int v = 0; v < 3; v++) {
        red[i] = parts[v];
        __syncthreads();
        for (int s = 64; s > 0; s >>= 1) {
            if (i < s) red[i] += red[i + s];
            __syncthreads();
        }
        d[v] = red[0];
        __syncthreads();
    }
    float dm = fmaxf(d[0], fmaxf(d[1], d[2]));
    float e0 = expf(d[0] - dm), e1 = expf(d[1] - dm), e2 = expf(d[2] - dm);
    float es = e0 + e1 + e2;
    float vag = (e0 * v0 + e1 * v1 + e2 * v2) / es;

    float part = 0.f;
    #pragma unroll
    for (int l = 0; l < Ll; l++) {
        part = fmaf(sh_head[l * Hh + i], fc_W[l * Hh + i], part);
        part = fmaf(sh_tail[l * Hh + i], fc_W[Ll * Hh + l * Hh + i], part);
    }
    part = fmaf(relv, fc_W[2 * Ll * Hh + i], part);
    part = fmaf(vag,  fc_W[2 * Ll * Hh + Hh + i], part);
    red[i] = part;
    __syncthreads();
    for (int s = 64; s > 0; s >>= 1) {
        if (i < s) red[i] += red[i + s];
        __syncthreads();
    }
    if (i == 0) out[b] = red[0] + fc_b[0];
}

// ---------------------------------------------------------------------------
extern "C" void kernel_launch(void* const* d_in, const int* in_sizes, int n_in,
                              void* d_out, int out_size) {
    const float* x         = (const float*)d_in[0];
    const float* W_rel     = (const float*)d_in[1];
    const float* W_self    = (const float*)d_in[2];
    const float* rel_table = (const float*)d_in[3];
    const float* Zn        = (const float*)d_in[4];
    const float* proj_W    = (const float*)d_in[5];
    const float* proj_b    = (const float*)d_in[6];
    const float* fc_W      = (const float*)d_in[7];
    const float* fc_b      = (const float*)d_in[8];
    const float* rep_seq   = (const float*)d_in[9];
    const int*   src       = (const int*)d_in[10];
    const int*   dst       = (const int*)d_in[11];
    const int*   etype     = (const int*)d_in[12];
    const int*   head_ids  = (const int*)d_in[14];
    const int*   tail_ids  = (const int*)d_in[15];
    const int*   rel_labels= (const int*)d_in[16];
    float* out = (float*)d_out;

    float* repr_base;
    cudaGetSymbolAddress((void**)&repr_base, g_repr);
    __half* w_base;
    cudaGetSymbolAddress((void**)&w_base, g_W);

    cudaFuncSetAttribute(rgcn_mma_gemm_kernel,
                         cudaFuncAttributeMaxDynamicSharedMemorySize, SM_TOTAL);

    // one-time per launch
    conv_w_kernel<<<(Ll * Hh * KK + 255) / 256, 256>>>(W_rel, W_self);
    xsplit_kernel<<<(Nn * Hh / 4 + 255) / 256, 256>>>(x);
    zero_cnt_kernel<<<NBINS / 256, 256>>>();
    count_kernel<<<(Ee + 255) / 256, 256>>>(dst);
    scan_kernel<<<1, 1024>>>();
    fill_kernel<<<(Ee + 255) / 256, 256>>>(src, dst, etype);

    const int gemm_blocks = Nn / 256;   // 125
    for (int l = 0; l < Ll; l++) {
        float* h_out = repr_base + (size_t)l * Nn * Hh;
        gather_kernel<<<(Nn * 32) / 256, 256>>>();
        rgcn_mma_gemm_kernel<<<gemm_blocks, 256, SM_TOTAL>>>(
            w_base + (size_t)l * Hh * KK,
            h_out,
            (l < Ll - 1) ? 1 : 0);
    }
    dim3 pool_grid(BSz * Ll, 8);
    pool_part_kernel<<<pool_grid, Hh>>>();
    pool_combine_kernel<<<BSz * Ll, Hh>>>();
    final_kernel<<<BSz, Hh>>>(rel_table, Zn, proj_W, proj_b, fc_W, fc_b,
                              rep_seq, head_ids, tail_ids, rel_labels, out);
}

// round 17
// speedup vs baseline: 1.1190x; 1.1190x over previous
#include <cuda_runtime.h>
#include <cuda_bf16.h>
#include <cuda_fp16.h>
#include <math.h>
#include <cstdint>

// Problem constants (fixed by setup_inputs)
#define Nn   32000
#define Hh   128
#define Ll   3
#define Rr   8
#define Ee   512000
#define BSz  32
#define Kk   64
#define NPG  1000
#define KK   1152        // R*H + H
#define NCHK 18          // K chunks of 64
#define NBINS 32768

// Scratch (device globals; no runtime allocation allowed)
__device__ float g_repr[(size_t)Ll * Nn * Hh];
__device__ float g_mean_buf[BSz * Ll * Hh];
__device__ float g_pool_part[BSz * Ll * 8 * Hh];
// A matrix fp16, CHUNK-MAJOR + SW128-swizzled: [chunk 18][node][64]
// chunks 0..15 = agg (rel r -> 2r,2r+1), 16,17 = self h
__device__ __half g_A[(size_t)NCHK * Nn * 64];
// Weights fp16, chunk-major swizzled: [L][chunk 18][n 128][64]
__device__ __half g_W[(size_t)Ll * Hh * KK];
// CSR by dst
__device__ int g_cnt[NBINS];
__device__ int g_off[NBINS];
__device__ int g_fill[NBINS];
__device__ uint32_t g_edges[Ee];   // src | (et << 16)

__device__ __forceinline__ uint32_t smem_to_u32(const void* smem_ptr) {
    uint32_t addr;
    asm("{ .reg .u64 tmp; cvta.to.shared.u64 tmp, %1; cvt.u32.u64 %0, tmp; }"
        : "=r"(addr) : "l"(smem_ptr));
    return addr;
}
#define MBARRIER_INIT(mbar, count) \
    asm volatile("mbarrier.init.shared.b64 [%0], %1;" \
        :: "r"((uint32_t)(mbar)), "r"((uint32_t)(count)) : "memory")
#define MBARRIER_EXPECT_TX(mbar, tx) \
    asm volatile("mbarrier.arrive.expect_tx.shared.b64 _, [%0], %1;" \
        :: "r"((uint32_t)(mbar)), "r"((uint32_t)(tx)) : "memory")
#define MBARRIER_WAIT_PARITY(mbar, parity) do { \
    uint32_t _mbar = (uint32_t)(mbar); \
    uint32_t _parity = (uint32_t)(parity); \
    uint32_t _done; \
    asm volatile( \
        "{\n\t.reg .pred p;\n\t" \
        "mbarrier.try_wait.parity.acquire.cta.shared::cta.b64 p, [%1], %2;\n\t" \
        "selp.b32 %0, 1, 0, p;\n\t}" \
        : "=r"(_done) : "r"(_mbar), "r"(_parity) : "memory"); \
    if (!_done) { \
        asm volatile( \
            "{\n\t.reg .pred P1;\n\t" \
            "WAIT_LOOP_%=:\n\t" \
            "mbarrier.try_wait.parity.acquire.cta.shared::cta.b64 P1, [%0], %1, 0x989680;\n\t" \
            "@P1 bra.uni WAIT_DONE_%=;\n\t" \
            "bra.uni WAIT_LOOP_%=;\n\t" \
            "WAIT_DONE_%=:\n\t}" \
            :: "r"(_mbar), "r"(_parity) : "memory"); \
    } \
} while(0)
__device__ __forceinline__ void bulkcp(uint32_t dst, const void* src,
                                       uint32_t bytes, uint32_t mbar) {
    asm volatile(
        "cp.async.bulk.shared::cluster.global.mbarrier::complete_tx::bytes "
        "[%0], [%1], %2, [%3];"
        :: "r"(dst), "l"(src), "r"(bytes), "r"(mbar) : "memory");
}

// swizzled element offset within a chunk row (64 fp16 = 128B row), row = node
__device__ __forceinline__ uint32_t swz64(int node, int c6) {
    return (uint32_t)(((((c6 >> 3) ^ (node & 7)) & 7) << 3) + (c6 & 7));
}

// ---------------------------------------------------------------------------
// CSR build (key = dst)
// ---------------------------------------------------------------------------
__global__ void zero_cnt_kernel() {
    int i = blockIdx.x * blockDim.x + threadIdx.x;
    g_cnt[i] = 0;
}
__global__ void count_kernel(const int* __restrict__ dst) {
    int e = blockIdx.x * blockDim.x + threadIdx.x;
    if (e < Ee) atomicAdd(&g_cnt[dst[e]], 1);
}
__global__ void scan_kernel() {
    __shared__ int wsum[32];
    int tid = threadIdx.x, lane = tid & 31, wid = tid >> 5;
    int carry = 0;
    for (int c = 0; c < NBINS / 1024; c++) {
        int idx = c * 1024 + tid;
        int v = g_cnt[idx];
        int incl = v;
        #pragma unroll
        for (int d = 1; d < 32; d <<= 1) {
            int n = __shfl_up_sync(0xffffffff, incl, d);
            if (lane >= d) incl += n;
        }
        if (lane == 31) wsum[wid] = incl;
        __syncthreads();
        if (wid == 0) {
            int s = wsum[lane];
            #pragma unroll
            for (int d = 1; d < 32; d <<= 1) {
                int n = __shfl_up_sync(0xffffffff, s, d);
                if (lane >= d) s += n;
            }
            wsum[lane] = s;
        }
        __syncthreads();
        int warp_prefix = wid ? wsum[wid - 1] : 0;
        int excl = carry + warp_prefix + incl - v;
        g_off[idx] = excl;
        g_fill[idx] = excl;
        carry += wsum[31];
        __syncthreads();
    }
}
__global__ void fill_kernel(const int* __restrict__ src,
                            const int* __restrict__ dst,
                            const int* __restrict__ et) {
    int e = blockIdx.x * blockDim.x + threadIdx.x;
    if (e >= Ee) return;
    int d = dst[e];
    int pos = atomicAdd(&g_fill[d], 1);
    g_edges[pos] = (uint32_t)src[e] | ((uint32_t)et[e] << 16);
}

// ---------------------------------------------------------------------------
// Weight pre-conversion into chunk-major swizzled layout, single fp16
// ---------------------------------------------------------------------------
__global__ void conv_w_kernel(const float* __restrict__ W_rel,
                              const float* __restrict__ W_self) {
    size_t idx = (size_t)blockIdx.x * blockDim.x + threadIdx.x;
    if (idx >= (size_t)Ll * Hh * KK) return;
    int k = (int)(idx % KK);
    int n = (int)((idx / KK) % Hh);
    int l = (int)(idx / ((size_t)KK * Hh));
    float w = (k < Rr * Hh)
        ? W_rel[((size_t)l * Rr * Hh + k) * Hh + n]
        : W_self[((size_t)l * Hh + (k - Rr * Hh)) * Hh + n];
    int chunk = k >> 6, c6 = k & 63;
    size_t o = ((size_t)(l * NCHK + chunk) * Hh + n) * 64 + swz64(n, c6);
    g_W[o] = __float2half(w);
}

// ---------------------------------------------------------------------------
// x -> fp16 into self chunks 16,17
// ---------------------------------------------------------------------------
__global__ void xsplit_kernel(const float* __restrict__ x) {
    int pos = blockIdx.x * blockDim.x + threadIdx.x;
    if (pos >= Nn * Hh / 4) return;
    int row = pos >> 5, c4 = (pos & 31) * 4;
    float4 v = *(const float4*)(x + (size_t)row * Hh + c4);
    __half h0 = __float2half(v.x), h1 = __float2half(v.y);
    __half h2 = __float2half(v.z), h3 = __float2half(v.w);
    uint2 u;
    u.x = (uint32_t)__half_as_ushort(h0) | ((uint32_t)__half_as_ushort(h1) << 16);
    u.y = (uint32_t)__half_as_ushort(h2) | ((uint32_t)__half_as_ushort(h3) << 16);
    int chunk = 16 + (c4 >> 6), c6 = c4 & 63;
    size_t o = ((size_t)chunk * Nn + row) * 64 + swz64(row, c6);
    *(uint2*)(g_A + o) = u;
}

// ---------------------------------------------------------------------------
// Gather: warp per dst node; 4-wide unrolled; fp32 h reads; fp16 chunk writes
// ---------------------------------------------------------------------------
__global__ __launch_bounds__(256)
void gather_kernel(const float* __restrict__ h) {
    int gw = (blockIdx.x * blockDim.x + threadIdx.x) >> 5;
    int lane = threadIdx.x & 31;
    if (gw >= Nn) return;
    int beg = g_off[gw];
    int cnt = g_cnt[gw];

    float4 a0 = {0,0,0,0}, a1 = {0,0,0,0}, a2 = {0,0,0,0}, a3 = {0,0,0,0};
    float4 a4 = {0,0,0,0}, a5 = {0,0,0,0}, a6 = {0,0,0,0}, a7 = {0,0,0,0};

    #define ACC_ADD(p, v) do { \
        switch ((p) >> 16) { \
            case 0: a0.x+=v.x; a0.y+=v.y; a0.z+=v.z; a0.w+=v.w; break; \
            case 1: a1.x+=v.x; a1.y+=v.y; a1.z+=v.z; a1.w+=v.w; break; \
            case 2: a2.x+=v.x; a2.y+=v.y; a2.z+=v.z; a2.w+=v.w; break; \
            case 3: a3.x+=v.x; a3.y+=v.y; a3.z+=v.z; a3.w+=v.w; break; \
            case 4: a4.x+=v.x; a4.y+=v.y; a4.z+=v.z; a4.w+=v.w; break; \
            case 5: a5.x+=v.x; a5.y+=v.y; a5.z+=v.z; a5.w+=v.w; break; \
            case 6: a6.x+=v.x; a6.y+=v.y; a6.z+=v.z; a6.w+=v.w; break; \
            default: a7.x+=v.x; a7.y+=v.y; a7.z+=v.z; a7.w+=v.w; break; \
        } \
    } while (0)

    for (int base = 0; base < cnt; base += 32) {
        int m = min(32, cnt - base);
        uint32_t myp = (lane < m) ? g_edges[beg + base + lane] : 0u;
        int j = 0;
        for (; j + 3 < m; j += 4) {
            uint32_t p0 = __shfl_sync(0xffffffffu, myp, j);
            uint32_t p1 = __shfl_sync(0xffffffffu, myp, j + 1);
            uint32_t p2 = __shfl_sync(0xffffffffu, myp, j + 2);
            uint32_t p3 = __shfl_sync(0xffffffffu, myp, j + 3);
            float4 v0 = *(const float4*)(h + (size_t)(p0 & 0xffffu) * Hh + lane * 4);
            float4 v1 = *(const float4*)(h + (size_t)(p1 & 0xffffu) * Hh + lane * 4);
            float4 v2 = *(const float4*)(h + (size_t)(p2 & 0xffffu) * Hh + lane * 4);
            float4 v3 = *(const float4*)(h + (size_t)(p3 & 0xffffu) * Hh + lane * 4);
            ACC_ADD(p0, v0); ACC_ADD(p1, v1); ACC_ADD(p2, v2); ACC_ADD(p3, v3);
        }
        for (; j < m; j++) {
            uint32_t p = __shfl_sync(0xffffffffu, myp, j);
            float4 v = *(const float4*)(h + (size_t)(p & 0xffffu) * Hh + lane * 4);
            ACC_ADD(p, v);
        }
    }
    #undef ACC_ADD

    // write: lane covers cols lane*4..lane*4+3 of 128; chunk = 2r + (lane>>4)
    int half_sel = lane >> 4;
    int c6 = (lane & 15) * 4;
    uint32_t sw = swz64(gw, c6);
    #define FP16_WRITE(acc, rr) do { \
        __half h0 = __float2half(acc.x), h1 = __float2half(acc.y); \
        __half h2 = __float2half(acc.z), h3 = __float2half(acc.w); \
        uint2 u; \
        u.x = (uint32_t)__half_as_ushort(h0) | ((uint32_t)__half_as_ushort(h1) << 16); \
        u.y = (uint32_t)__half_as_ushort(h2) | ((uint32_t)__half_as_ushort(h3) << 16); \
        size_t o = ((size_t)(2 * (rr) + half_sel) * Nn + gw) * 64 + sw; \
        *(uint2*)(g_A + o) = u; \
    } while (0)
    FP16_WRITE(a0, 0); FP16_WRITE(a1, 1); FP16_WRITE(a2, 2); FP16_WRITE(a3, 3);
    FP16_WRITE(a4, 4); FP16_WRITE(a5, 5); FP16_WRITE(a6, 6); FP16_WRITE(a7, 7);
    #undef FP16_WRITE
}

// ---------------------------------------------------------------------------
// mma.sync fp16 GEMM with cp.async.bulk staging, single pass.
// CTA: 256 rows x 128 cols, 8 warps (4M x 2N), warp tile 64x64.
// 18 chunks of K=64; 4-deep mbarrier pipeline.
// ---------------------------------------------------------------------------
#define TILE_A 32768                 // 256 rows * 128B
#define TILE_B 16384                 // 128 rows * 128B
#define STAGEB (TILE_A + TILE_B)     // 49152
#define NSTAGE 4
#define MBAR_OFF (NSTAGE * STAGEB)   // 196608
#define SM_TOTAL (MBAR_OFF + 64)

__device__ __forceinline__ void ldsm_x4(uint32_t* r, uint32_t addr) {
    asm volatile("ldmatrix.sync.aligned.m8n8.x4.shared.b16 {%0,%1,%2,%3}, [%4];"
                 : "=r"(r[0]), "=r"(r[1]), "=r"(r[2]), "=r"(r[3]) : "r"(addr));
}
__device__ __forceinline__ void ldsm_x2(uint32_t* r, uint32_t addr) {
    asm volatile("ldmatrix.sync.aligned.m8n8.x2.shared.b16 {%0,%1}, [%2];"
                 : "=r"(r[0]), "=r"(r[1]) : "r"(addr));
}
__device__ __forceinline__ void mma16816f16(float* c, const uint32_t* a, const uint32_t* b) {
    asm volatile(
        "mma.sync.aligned.m16n8k16.row.col.f32.f16.f16.f32 "
        "{%0,%1,%2,%3}, {%4,%5,%6,%7}, {%8,%9}, {%0,%1,%2,%3};"
        : "+f"(c[0]), "+f"(c[1]), "+f"(c[2]), "+f"(c[3])
        : "r"(a[0]), "r"(a[1]), "r"(a[2]), "r"(a[3]), "r"(b[0]), "r"(b[1]));
}

__global__ __launch_bounds__(256, 1)
void rgcn_mma_gemm_kernel(const __half* __restrict__ W,   // layer chunk-major
                          float* __restrict__ out,
                          int write_self) {
    extern __shared__ char dsm[];
    const uint32_t sb = smem_to_u32(dsm);
    const int tid  = threadIdx.x;
    const int wid  = tid >> 5;
    const int lane = tid & 31;
    const int warp_m = wid >> 1;       // 0..3 (64-row tiles)
    const int warp_n = wid & 1;        // 0..1 (64-col tiles)
    const int row0 = blockIdx.x * 256;

    if (tid == 0) {
        #pragma unroll
        for (int s = 0; s < NSTAGE; s++) MBARRIER_INIT(sb + MBAR_OFF + s * 8, 1);
    }
    asm volatile("fence.proxy.async.shared::cta;" ::: "memory");
    __syncthreads();

    auto issue = [&](int t, int slot) {
        if (tid == 0) {
            uint32_t mbar = sb + MBAR_OFF + slot * 8;
            MBARRIER_EXPECT_TX(mbar, STAGEB);
            uint32_t s = sb + slot * STAGEB;
            const __half* a = g_A + ((size_t)t * Nn + row0) * 64;
            bulkcp(s,          a, TILE_A, mbar);
            bulkcp(s + TILE_A, W + (size_t)t * Hh * 64, TILE_B, mbar);
        }
    };

    float acc[4][8][4];
    #pragma unroll
    for (int mt = 0; mt < 4; mt++)
        #pragma unroll
        for (int nt = 0; nt < 8; nt++)
            #pragma unroll
            for (int j = 0; j < 4; j++) acc[mt][nt][j] = 0.f;

    issue(0, 0);
    issue(1, 1);
    issue(2, 2);
    issue(3, 3);

    for (int t = 0; t < NCHK; t++) {
        int slot = t % NSTAGE;
        MBARRIER_WAIT_PARITY(sb + MBAR_OFF + slot * 8, (t / NSTAGE) & 1);

        uint32_t S  = sb + slot * STAGEB;
        uint32_t AH = S;
        uint32_t BH = S + TILE_A;

        #pragma unroll
        for (int ks = 0; ks < 4; ks++) {
            uint32_t bf[8][2];
            {
                int cb = (lane >> 3) & 1;
                #pragma unroll
                for (int nt = 0; nt < 8; nt++) {
                    int nl = warp_n * 64 + nt * 8 + (lane & 7);
                    uint32_t a = (uint32_t)(nl * 128 + (((ks * 2 + cb) ^ (nl & 7)) << 4));
                    ldsm_x2(bf[nt], BH + a);
                }
            }
            uint32_t af[4][4];
            int cb = lane >> 4;
            #pragma unroll
            for (int mt = 0; mt < 4; mt++) {
                int rl = warp_m * 64 + mt * 16 + (lane & 15);
                ldsm_x4(af[mt], AH + (uint32_t)(rl * 128 + (((ks * 2 + cb) ^ (rl & 7)) << 4)));
            }
            #pragma unroll
            for (int mt = 0; mt < 4; mt++)
                #pragma unroll
                for (int nt = 0; nt < 8; nt++)
                    mma16816f16(acc[mt][nt], af[mt], bf[nt]);
        }
        __syncthreads();                 // all warps done with this slot
        if (t + NSTAGE < NCHK) issue(t + NSTAGE, slot);
    }

    // ---- epilogue: relu + fp32 repr (+ fp16 self chunks unless last layer) ----
    #pragma unroll
    for (int mt = 0; mt < 4; mt++) {
        int row = row0 + warp_m * 64 + mt * 16 + (lane >> 2);
        #pragma unroll
        for (int nt = 0; nt < 8; nt++) {
            int col = warp_n * 64 + nt * 8 + (lane & 3) * 2;
            int chunk = 16 + (col >> 6), c6 = col & 63;
            #pragma unroll
            for (int half_i = 0; half_i < 2; half_i++) {
                int rr = row + half_i * 8;
                float ox = fmaxf(acc[mt][nt][half_i * 2 + 0], 0.f);
                float oy = fmaxf(acc[mt][nt][half_i * 2 + 1], 0.f);
                *(float2*)(out + (size_t)rr * Hh + col) = make_float2(ox, oy);
                if (write_self) {
                    __half h0 = __float2half(ox);
                    __half h1 = __float2half(oy);
                    uint32_t u = (uint32_t)__half_as_ushort(h0) | ((uint32_t)__half_as_ushort(h1) << 16);
                    size_t so = ((size_t)chunk * Nn + rr) * 64 + swz64(rr, c6);
                    *(uint32_t*)(g_A + so) = u;
                }
            }
        }
    }
}

// ---------------------------------------------------------------------------
// Mean pooling: two-stage deterministic
// ---------------------------------------------------------------------------
__global__ void pool_part_kernel() {
    int bl = blockIdx.x;
    int ck = blockIdx.y;
    int b = bl / Ll, l = bl % Ll, i = threadIdx.x;
    int n0 = ck * (NPG / 8);
    const float* p = g_repr + (size_t)l * Nn * Hh + (size_t)(b * NPG + n0) * Hh + i;
    float s = 0.f;
    for (int n = 0; n < NPG / 8; n++) s += p[(size_t)n * Hh];
    g_pool_part[(bl * 8 + ck) * Hh + i] = s;
}
__global__ void pool_combine_kernel() {
    int bl = blockIdx.x, i = threadIdx.x;
    float s = 0.f;
    #pragma unroll
    for (int ck = 0; ck < 8; ck++) s += g_pool_part[(bl * 8 + ck) * Hh + i];
    g_mean_buf[bl * Hh + i] = s * (1.0f / NPG);
}

// ---------------------------------------------------------------------------
// Fused final head
// ---------------------------------------------------------------------------
__global__ void final_kernel(const float* __restrict__ rel_table,
                             const float* __restrict__ Zn,
                             const float* __restrict__ proj_W,
                             const float* __restrict__ proj_b,
                             const float* __restrict__ fc_W,
                             const float* __restrict__ fc_b,
                             const float* __restrict__ rep_seq,
                             const int* __restrict__ head_ids,
                             const int* __restrict__ tail_ids,
                             const int* __restrict__ rel_labels,
                             float* __restrict__ out)
{
    int b = blockIdx.x, i = threadIdx.x;
    __shared__ float sh_head[Ll * Hh], sh_tail[Ll * Hh], sh_gm[Ll * Hh];
    __shared__ float sh_gout[Hh], sh_hout[Hh], sh_tout[Hh];
    __shared__ float sh_e1[Kk], sh_e2[Kk];
    __shared__ float red[Hh];

    int head = head_ids[b], tail = tail_ids[b], rl = rel_labels[b];

    for (int j = i; j < Ll * Hh; j += Hh) {
        int l = j >> 7, c = j & 127;
        sh_head[j] = g_repr[(size_t)l * Nn * Hh + (size_t)head * Hh + c];
        sh_tail[j] = g_repr[(size_t)l * Nn * Hh + (size_t)tail * Hh + c];
        sh_gm[j]   = g_mean_buf[(b * Ll + l) * Hh + c];
    }
    __syncthreads();

    float bias = proj_b[i];
    float ag = bias, ah = bias, at = bias;
    for (int j = 0; j < Ll * Hh; j++) {
        float w = proj_W[j * Hh + i];
        ag = fmaf(sh_gm[j],   w, ag);
        ah = fmaf(sh_head[j], w, ah);
        at = fmaf(sh_tail[j], w, at);
    }
    sh_gout[i] = (ag >= 0.f) ? ag : 0.01f * ag;
    sh_hout[i] = ah;
    sh_tout[i] = at;
    __syncthreads();

    float lg1 = 0.f, lg2 = 0.f;
    if (i < Kk) {
        const float* z = Zn + (size_t)i * Hh;
        for (int c = 0; c < Hh; c++) {
            lg1 = fmaf(sh_hout[c], z[c], lg1);
            lg2 = fmaf(sh_tout[c], z[c], lg2);
        }
        sh_e1[i] = lg1; sh_e2[i] = lg2;
    }
    __syncthreads();
    float m1 = -1e30f, m2 = -1e30f;
    for (int k = 0; k < Kk; k++) {
        m1 = fmaxf(m1, sh_e1[k]);
        m2 = fmaxf(m2, sh_e2[k]);
    }
    __syncthreads();
    if (i < Kk) { sh_e1[i] = expf(lg1 - m1); sh_e2[i] = expf(lg2 - m2); }
    __syncthreads();
    float sum1 = 0.f, sum2 = 0.f;
    for (int k = 0; k < Kk; k++) { sum1 += sh_e1[k]; sum2 += sh_e2[k]; }
    float a1 = 0.f, a2 = 0.f;
    for (int k = 0; k < Kk; k++) {
        float zi = Zn[(size_t)k * Hh + i];
        a1 = fmaf(sh_e1[k], zi, a1);
        a2 = fmaf(sh_e2[k], zi, a2);
    }
    a1 /= sum1; a2 /= sum2;
    float sview = (1.f / (1.f + expf(-a1))) * (1.f / (1.f + expf(-a2)));

    float relv = rel_table[(size_t)rl * Hh + i];
    float v0 = sh_gout[i];
    float v1 = rep_seq[(size_t)b * Hh + i];
    float v2 = sview;

    float d[3];
    float parts[3] = {relv * v0, relv * v1, relv * v2};
    #pragma unroll
    for (int v = 0; v < 3; v++) {
        red[i] = parts[v];
        __syncthreads();
        for (int s = 64; s > 0; s >>= 1) {
            if (i < s) red[i] += red[i + s];
            __syncthreads();
        }
        d[v] = red[0];
        __syncthreads();
    }
    float dm = fmaxf(d[0], fmaxf(d[1], d[2]));
    float e0 = expf(d[0] - dm), e1 = expf(d[1] - dm), e2 = expf(d[2] - dm);
    float es = e0 + e1 + e2;
    float vag = (e0 * v0 + e1 * v1 + e2 * v2) / es;

    float part = 0.f;
    #pragma unroll
    for (int l = 0; l < Ll; l++) {
        part = fmaf(sh_head[l * Hh + i], fc_W[l * Hh + i], part);
        part = fmaf(sh_tail[l * Hh + i], fc_W[Ll * Hh + l * Hh + i], part);
    }
    part = fmaf(relv, fc_W[2 * Ll * Hh + i], part);
    part = fmaf(vag,  fc_W[2 * Ll * Hh + Hh + i], part);
    red[i] = part;
    __syncthreads();
    for (int s = 64; s > 0; s >>= 1) {
        if (i < s) red[i] += red[i + s];
        __syncthreads();
    }
    if (i == 0) out[b] = red[0] + fc_b[0];
}

// ---------------------------------------------------------------------------
extern "C" void kernel_launch(void* const* d_in, const int* in_sizes, int n_in,
                              void* d_out, int out_size) {
    const float* x         = (const float*)d_in[0];
    const float* W_rel     = (const float*)d_in[1];
    const float* W_self    = (const float*)d_in[2];
    const float* rel_table = (const float*)d_in[3];
    const float* Zn        = (const float*)d_in[4];
    const float* proj_W    = (const float*)d_in[5];
    const float* proj_b    = (const float*)d_in[6];
    const float* fc_W      = (const float*)d_in[7];
    const float* fc_b      = (const float*)d_in[8];
    const float* rep_seq   = (const float*)d_in[9];
    const int*   src       = (const int*)d_in[10];
    const int*   dst       = (const int*)d_in[11];
    const int*   etype     = (const int*)d_in[12];
    const int*   head_ids  = (const int*)d_in[14];
    const int*   tail_ids  = (const int*)d_in[15];
    const int*   rel_labels= (const int*)d_in[16];
    float* out = (float*)d_out;

    float* repr_base;
    cudaGetSymbolAddress((void**)&repr_base, g_repr);
    __half* w_base;
    cudaGetSymbolAddress((void**)&w_base, g_W);

    cudaFuncSetAttribute(rgcn_mma_gemm_kernel,
                         cudaFuncAttributeMaxDynamicSharedMemorySize, SM_TOTAL);

    // one-time per launch
    conv_w_kernel<<<(Ll * Hh * KK + 255) / 256, 256>>>(W_rel, W_self);
    xsplit_kernel<<<(Nn * Hh / 4 + 255) / 256, 256>>>(x);
    zero_cnt_kernel<<<NBINS / 256, 256>>>();
    count_kernel<<<(Ee + 255) / 256, 256>>>(dst);
    scan_kernel<<<1, 1024>>>();
    fill_kernel<<<(Ee + 255) / 256, 256>>>(src, dst, etype);

    const int gemm_blocks = Nn / 256;   // 125
    for (int l = 0; l < Ll; l++) {
        const float* h_in = (l == 0) ? x : (repr_base + (size_t)(l - 1) * Nn * Hh);
        float* h_out = repr_base + (size_t)l * Nn * Hh;
        gather_kernel<<<(Nn * 32) / 256, 256>>>(h_in);
        rgcn_mma_gemm_kernel<<<gemm_blocks, 256, SM_TOTAL>>>(
            w_base + (size_t)l * Hh * KK,
            h_out,
            (l < Ll - 1) ? 1 : 0);
    }
    dim3 pool_grid(BSz * Ll, 8);
    pool_part_kernel<<<pool_grid, Hh>>>();
    pool_combine_kernel<<<BSz * Ll, Hh>>>();
    final_kernel<<<BSz, Hh>>>(rel_table, Zn, proj_W, proj_b, fc_W, fc_b,
                              rep_seq, head_ids, tail_ids, rel_labels, out);
}